// round 1
// baseline (speedup 1.0000x reference)
#include <cuda_runtime.h>
#include <math.h>

#define NN 1024
#define THREADS 256
#define ELEMS_PER_THREAD (NN / THREADS)          // 4
#define PAIRS_PER_THREAD ((NN / 2) / THREADS)    // 2

// Butterfly network, depth-2, N=1024.
// One row per CTA; row lives in shared memory as float2 (re, im), ping-pong
// between two buffers so each factor needs exactly one __syncthreads().
//
// Perm factor (size m): reference does (1) even/odd mix with p0 then
// (2) per-half reversal mix with p1/p2. Composed into a single gather:
//   out[j] = (1-pr)*[(1-p0)h[j] + p0 h[s(j)]] + pr*[(1-p0)h[r(j)] + p0 h[s(r(j))]]
// with s(j) the perfect-shuffle source and r(j) the within-half reversal.
//
// Diag factor (size m): complex 2x2 per k:
//   [y0;y1] = [[A,B],[C,D]] [x0;x1],  x0=h[blk+k], x1=h[blk+half+k]
// owner-computes-pair: one thread produces both outputs of a pair.
__global__ __launch_bounds__(THREADS) void butterfly_kernel(
    const float* __restrict__ x,
    const float* __restrict__ perm_logit,
    const float* __restrict__ abcd,
    const float* __restrict__ bias,
    float* __restrict__ out,
    int depth)
{
    __shared__ float2 buf[2][NN];
    const int row = blockIdx.x;
    const int t = threadIdx.x;

    // ---- load row, imag = 0 ----
    {
        const float* xr = x + (size_t)row * NN;
        #pragma unroll
        for (int u = 0; u < ELEMS_PER_THREAD; ++u) {
            int i = t + u * THREADS;
            buf[0][i] = make_float2(xr[i], 0.0f);
        }
    }
    int cur = 0;
    __syncthreads();

    for (int d = 0; d < depth; ++d) {
        const float p0 = 1.0f / (1.0f + expf(-perm_logit[d * 3 + 0]));
        const float p1 = 1.0f / (1.0f + expf(-perm_logit[d * 3 + 1]));
        const float p2 = 1.0f / (1.0f + expf(-perm_logit[d * 3 + 2]));

        // ---- perm factors, m = 4, 8, ..., 1024 (composed eo + reversal) ----
        for (int m = 4; m <= NN; m <<= 1) {
            const int half = m >> 1;
            const int nxt = cur ^ 1;
            #pragma unroll
            for (int u = 0; u < ELEMS_PER_THREAD; ++u) {
                int i = t + u * THREADS;
                int blk = i & ~(m - 1);
                int j = i - blk;
                bool second = (j >= half);
                float pr = second ? p2 : p1;
                int sj  = second ? (2 * (j - half) + 1) : (2 * j);
                int rj  = second ? (m + half - 1 - j)   : (half - 1 - j);
                int srj = second ? (2 * (rj - half) + 1) : (2 * rj);
                float2 a  = buf[cur][blk + j];
                float2 bb = buf[cur][blk + sj];
                float2 c  = buf[cur][blk + rj];
                float2 dd = buf[cur][blk + srj];
                float ex = a.x + p0 * (bb.x - a.x);
                float ey = a.y + p0 * (bb.y - a.y);
                float fx = c.x + p0 * (dd.x - c.x);
                float fy = c.y + p0 * (dd.y - c.y);
                buf[nxt][i] = make_float2(ex + pr * (fx - ex),
                                          ey + pr * (fy - ey));
            }
            __syncthreads();
            cur = nxt;
        }

        // ---- diag factors, m = 2, 4, ..., 1024 ----
        // abcd layout per depth: concatenated factor blocks, factor of size m
        // at complex offset (4*NN - 4*m), shape (2,2,m/2) complex.
        const float2* abd = (const float2*)(abcd) + (size_t)d * (4 * NN - 4);
        int lh = 0;  // log2(half)
        for (int m = 2; m <= NN; m <<= 1, ++lh) {
            const int half = m >> 1;
            const float2* W = abd + (4 * NN - 4 * m);
            const int nxt = cur ^ 1;
            #pragma unroll
            for (int u = 0; u < PAIRS_PER_THREAD; ++u) {
                int p  = t + u * THREADS;        // global pair index 0..NN/2-1
                int bi = p >> lh;                // block index
                int k  = p & (half - 1);         // k within block
                int i0 = bi * m + k;
                int i1 = i0 + half;
                float2 x0 = buf[cur][i0];
                float2 x1 = buf[cur][i1];
                float2 A  = W[k];
                float2 Bw = W[half + k];
                float2 C  = W[2 * half + k];
                float2 D  = W[3 * half + k];
                float2 y0, y1;
                y0.x = A.x * x0.x - A.y * x0.y + Bw.x * x1.x - Bw.y * x1.y;
                y0.y = A.x * x0.y + A.y * x0.x + Bw.x * x1.y + Bw.y * x1.x;
                y1.x = C.x * x0.x - C.y * x0.y + D.x * x1.x - D.y * x1.y;
                y1.y = C.x * x0.y + C.y * x0.x + D.x * x1.y + D.y * x1.x;
                buf[nxt][i0] = y0;
                buf[nxt][i1] = y1;
            }
            __syncthreads();
            cur = nxt;
        }
    }

    // ---- store real part + bias ----
    {
        float* orow = out + (size_t)row * NN;
        #pragma unroll
        for (int u = 0; u < ELEMS_PER_THREAD; ++u) {
            int i = t + u * THREADS;
            orow[i] = bias[i] + buf[cur][i].x;
        }
    }
}

extern "C" void kernel_launch(void* const* d_in, const int* in_sizes, int n_in,
                              void* d_out, int out_size)
{
    const float* x          = (const float*)d_in[0];  // (B, 1024)
    const float* perm_logit = (const float*)d_in[1];  // (DEPTH, 3)
    const float* abcd       = (const float*)d_in[2];  // (DEPTH, 4092, 2)
    const float* bias       = (const float*)d_in[3];  // (1024,)
    float* out = (float*)d_out;

    int B = in_sizes[0] / NN;
    int depth = in_sizes[1] / 3;

    butterfly_kernel<<<B, THREADS>>>(x, perm_logit, abcd, bias, out, depth);
}

// round 7
// speedup vs baseline: 1.9644x; 1.9644x over previous
#include <cuda_runtime.h>
#include <cuda_bf16.h>
#include <math.h>
#include <stdint.h>

#define NN 1024
#define BT 256  // threads for butterfly kernel

// ---------------- scratch (__device__ globals; no runtime alloc) ----------------
__device__ float          g_W[NN * NN];            // 4 MB : M[k][n] (row k = butterfly(e_k))
__device__ __nv_bfloat16  g_BhT[NN * NN];          // 2 MB : hi,  [n][k]
__device__ __nv_bfloat16  g_BlT[NN * NN];          // 2 MB : lo residual, [n][k]
__device__ __nv_bfloat16  g_xh[16384 * NN];        // 32 MB
__device__ __nv_bfloat16  g_xl[16384 * NN];        // 32 MB

// ---------------- PTX helpers (all family-agnostic: sm_80+ features) ----------------
__device__ __forceinline__ uint32_t smem_u32(const void* p) {
    uint32_t a;
    asm("{ .reg .u64 t; cvta.to.shared.u64 t, %1; cvt.u32.u64 %0, t; }" : "=r"(a) : "l"(p));
    return a;
}
#define CP_ASYNC16(s, g) \
    asm volatile("cp.async.cg.shared.global [%0], [%1], 16;" :: "r"(s), "l"(g))
#define CP_COMMIT() asm volatile("cp.async.commit_group;" ::: "memory")
#define CP_WAIT1()  asm volatile("cp.async.wait_group 1;" ::: "memory")
#define CP_WAIT0()  asm volatile("cp.async.wait_group 0;" ::: "memory")
#define LDSM4(r, addr) \
    asm volatile("ldmatrix.sync.aligned.m8n8.x4.shared.b16 {%0,%1,%2,%3}, [%4];" \
        : "=r"((r)[0]), "=r"((r)[1]), "=r"((r)[2]), "=r"((r)[3]) : "r"(addr))
#define MMA16816(d, a, b) \
    asm volatile("mma.sync.aligned.m16n8k16.row.col.f32.bf16.bf16.f32 " \
        "{%0,%1,%2,%3}, {%4,%5,%6,%7}, {%8,%9}, {%0,%1,%2,%3};" \
        : "+f"((d)[0]), "+f"((d)[1]), "+f"((d)[2]), "+f"((d)[3]) \
        : "r"((a)[0]), "r"((a)[1]), "r"((a)[2]), "r"((a)[3]), "r"((b)[0]), "r"((b)[1]))

// ================= butterfly on identity rows -> g_W =================
__global__ __launch_bounds__(BT) void butterfly_ident_kernel(
    const float* __restrict__ perm_logit, const float* __restrict__ abcd, int depth)
{
    __shared__ float2 buf[2][NN];
    const int row = blockIdx.x;
    const int t = threadIdx.x;
    #pragma unroll
    for (int u = 0; u < NN / BT; ++u) {
        int i = t + u * BT;
        buf[0][i] = make_float2(i == row ? 1.0f : 0.0f, 0.0f);
    }
    int cur = 0;
    __syncthreads();

    for (int d = 0; d < depth; ++d) {
        const float p0 = 1.0f / (1.0f + expf(-perm_logit[d * 3 + 0]));
        const float p1 = 1.0f / (1.0f + expf(-perm_logit[d * 3 + 1]));
        const float p2 = 1.0f / (1.0f + expf(-perm_logit[d * 3 + 2]));
        for (int m = 4; m <= NN; m <<= 1) {
            const int half = m >> 1;
            const int nxt = cur ^ 1;
            #pragma unroll
            for (int u = 0; u < NN / BT; ++u) {
                int i = t + u * BT;
                int blk = i & ~(m - 1);
                int j = i - blk;
                bool second = (j >= half);
                float pr = second ? p2 : p1;
                int sj  = second ? (2 * (j - half) + 1) : (2 * j);
                int rj  = second ? (m + half - 1 - j)   : (half - 1 - j);
                int srj = second ? (2 * (rj - half) + 1) : (2 * rj);
                float2 a  = buf[cur][blk + j];
                float2 bb = buf[cur][blk + sj];
                float2 c  = buf[cur][blk + rj];
                float2 dd = buf[cur][blk + srj];
                float ex = a.x + p0 * (bb.x - a.x);
                float ey = a.y + p0 * (bb.y - a.y);
                float fx = c.x + p0 * (dd.x - c.x);
                float fy = c.y + p0 * (dd.y - c.y);
                buf[nxt][i] = make_float2(ex + pr * (fx - ex), ey + pr * (fy - ey));
            }
            __syncthreads();
            cur = nxt;
        }
        const float2* abd = (const float2*)(abcd) + (size_t)d * (4 * NN - 4);
        int lh = 0;
        for (int m = 2; m <= NN; m <<= 1, ++lh) {
            const int half = m >> 1;
            const float2* W = abd + (4 * NN - 4 * m);
            const int nxt = cur ^ 1;
            #pragma unroll
            for (int u = 0; u < (NN / 2) / BT; ++u) {
                int p  = t + u * BT;
                int bi = p >> lh;
                int k  = p & (half - 1);
                int i0 = bi * m + k;
                int i1 = i0 + half;
                float2 x0 = buf[cur][i0];
                float2 x1 = buf[cur][i1];
                float2 A  = W[k];
                float2 Bw = W[half + k];
                float2 C  = W[2 * half + k];
                float2 D  = W[3 * half + k];
                float2 y0, y1;
                y0.x = A.x * x0.x - A.y * x0.y + Bw.x * x1.x - Bw.y * x1.y;
                y0.y = A.x * x0.y + A.y * x0.x + Bw.x * x1.y + Bw.y * x1.x;
                y1.x = C.x * x0.x - C.y * x0.y + D.x * x1.x - D.y * x1.y;
                y1.y = C.x * x0.y + C.y * x0.x + D.x * x1.y + D.y * x1.x;
                buf[nxt][i0] = y0;
                buf[nxt][i1] = y1;
            }
            __syncthreads();
            cur = nxt;
        }
    }
    #pragma unroll
    for (int u = 0; u < NN / BT; ++u) {
        int i = t + u * BT;
        g_W[(size_t)row * NN + i] = buf[cur][i].x;
    }
}

// ================= convert W -> transposed bf16 split =================
__global__ void convW_kernel()
{
    __shared__ float tile[32][33];
    int tx = threadIdx.x, ty = threadIdx.y;
    int bx = blockIdx.x, by = blockIdx.y;
    #pragma unroll
    for (int k = 0; k < 4; ++k) {
        int krow = by * 32 + ty + 8 * k;
        tile[ty + 8 * k][tx] = g_W[(size_t)krow * NN + bx * 32 + tx];
    }
    __syncthreads();
    #pragma unroll
    for (int k = 0; k < 4; ++k) {
        int n  = bx * 32 + ty + 8 * k;
        int kk = by * 32 + tx;
        float v = tile[tx][ty + 8 * k];
        __nv_bfloat16 h = __float2bfloat16(v);
        float r = v - __bfloat162float(h);
        g_BhT[(size_t)n * NN + kk] = h;
        g_BlT[(size_t)n * NN + kk] = __float2bfloat16(r);
    }
}

// ================= convert x -> bf16 split =================
__global__ void convX_kernel(const float* __restrict__ x, int n4)
{
    int i = blockIdx.x * blockDim.x + threadIdx.x;
    if (i >= n4) return;
    float4 v = ((const float4*)x)[i];
    __nv_bfloat16 h0 = __float2bfloat16(v.x);
    __nv_bfloat16 h1 = __float2bfloat16(v.y);
    __nv_bfloat16 h2 = __float2bfloat16(v.z);
    __nv_bfloat16 h3 = __float2bfloat16(v.w);
    __nv_bfloat162* dh = (__nv_bfloat162*)g_xh + i * 2;
    __nv_bfloat162* dl = (__nv_bfloat162*)g_xl + i * 2;
    dh[0] = __nv_bfloat162(h0, h1);
    dh[1] = __nv_bfloat162(h2, h3);
    dl[0] = __nv_bfloat162(__float2bfloat16(v.x - __bfloat162float(h0)),
                           __float2bfloat16(v.y - __bfloat162float(h1)));
    dl[1] = __nv_bfloat162(__float2bfloat16(v.z - __bfloat162float(h2)),
                           __float2bfloat16(v.w - __bfloat162float(h3)));
}

// ================= HMMA GEMM: out = xh*Wh + xh*Wl + xl*Wh + bias =================
// CTA tile 128x128, K-stage 32, double-buffered cp.async. 8 warps, warp tile 32x64.
// Smem rows padded to 40 bf16 (80B) -> conflict-free ldmatrix (r*20 mod 32 distinct).
#define TM 128
#define TN 128
#define TK 32
#define PAD 40
#define AST (TM * PAD)          // bf16 elems per A stage
#define BST (TN * PAD)
#define CHUNKS_PER_PASS (NN / TK)       // 32
#define NSTAGES_TOT (3 * CHUNKS_PER_PASS)  // 96

__global__ __launch_bounds__(256) void gemm_kernel(
    const float* __restrict__ bias, float* __restrict__ out)
{
    __shared__ __nv_bfloat16 As[2 * AST];   // 20 KB
    __shared__ __nv_bfloat16 Bs[2 * BST];   // 20 KB

    const int tid = threadIdx.x;
    const int lane = tid & 31;
    const int wid = tid >> 5;
    const int wm = wid & 3;       // 4 warps over M (32 rows each)
    const int wn = wid >> 2;      // 2 warps over N (64 cols each)
    const int gn = blockIdx.x;    // N block (fast) -> A reuse in L2
    const int gm = blockIdx.y;    // M block

    float acc[2][8][4];
    #pragma unroll
    for (int mf = 0; mf < 2; ++mf)
        #pragma unroll
        for (int nf = 0; nf < 8; ++nf)
            #pragma unroll
            for (int q = 0; q < 4; ++q) acc[mf][nf][q] = 0.0f;

    const uint32_t sAbase = smem_u32(As);
    const uint32_t sBbase = smem_u32(Bs);

    // cp.async mapping: 512 16B-chunks per tile; thread t handles chunks t and t+256.
    const int r0  = tid >> 2;           // row 0..63
    const int cc0 = tid & 3;            // 16B chunk within 64B row window
    const uint32_t w0 = (uint32_t)(r0 * 80 + cc0 * 16);
    const uint32_t w1 = w0 + 64 * 80;

    const __nv_bfloat16* const Aps[3] = { g_xh, g_xh, g_xl };
    const __nv_bfloat16* const Bps[3] = { g_BhT, g_BlT, g_BhT };

    auto issue = [&](int s) {
        const int pass = s >> 5;                       // 32 chunks per pass
        const int k0 = (s & (CHUNKS_PER_PASS - 1)) * TK;
        const __nv_bfloat16* Ap = Aps[pass] + (size_t)(gm * TM) * NN + k0;
        const __nv_bfloat16* Bp = Bps[pass] + (size_t)(gn * TN) * NN + k0;
        const uint32_t sa = sAbase + (uint32_t)((s & 1) * AST * 2);
        const uint32_t sb = sBbase + (uint32_t)((s & 1) * BST * 2);
        CP_ASYNC16(sa + w0, Ap + (size_t)r0 * NN + cc0 * 8);
        CP_ASYNC16(sa + w1, Ap + (size_t)(r0 + 64) * NN + cc0 * 8);
        CP_ASYNC16(sb + w0, Bp + (size_t)r0 * NN + cc0 * 8);
        CP_ASYNC16(sb + w1, Bp + (size_t)(r0 + 64) * NN + cc0 * 8);
        CP_COMMIT();
    };

    // ldmatrix lane address components
    const int a_r = (lane & 7) | (((lane >> 3) & 1) << 3);   // row 0..15 within frag
    const int a_c = ((lane >> 4) & 1) * 8;                   // +8 elems for mats 2,3
    const int b_n = (lane & 7) | (((lane >> 4) & 1) << 3);   // n row within 16
    const int b_k = ((lane >> 3) & 1) * 8;                   // +8 elems for mats 1,3
    const uint32_t aoff = (uint32_t)((wm * 32 + a_r) * 80 + a_c * 2);
    const uint32_t boff = (uint32_t)((wn * 64 + b_n) * 80 + b_k * 2);

    issue(0);
    for (int s = 0; s < NSTAGES_TOT; ++s) {
        if (s + 1 < NSTAGES_TOT) { issue(s + 1); CP_WAIT1(); }
        else                     { CP_WAIT0(); }
        __syncthreads();
        const uint32_t sa = sAbase + (uint32_t)((s & 1) * AST * 2) + aoff;
        const uint32_t sb = sBbase + (uint32_t)((s & 1) * BST * 2) + boff;
        #pragma unroll
        for (int kk = 0; kk < 2; ++kk) {
            uint32_t af[2][4];
            LDSM4(af[0], sa + kk * 32);
            LDSM4(af[1], sa + kk * 32 + 16 * 80);
            uint32_t bf[4][4];
            #pragma unroll
            for (int g2 = 0; g2 < 4; ++g2)
                LDSM4(bf[g2], sb + kk * 32 + g2 * 16 * 80);
            #pragma unroll
            for (int mf = 0; mf < 2; ++mf)
                #pragma unroll
                for (int nf = 0; nf < 8; ++nf) {
                    uint32_t bb[2] = { bf[nf >> 1][(nf & 1) * 2],
                                       bf[nf >> 1][(nf & 1) * 2 + 1] };
                    MMA16816(acc[mf][nf], af[mf], bb);
                }
        }
        __syncthreads();
    }

    // epilogue: add bias, store fp32
    const int row0 = gm * TM + wm * 32 + (lane >> 2);
    const int col0 = gn * TN + wn * 64 + (lane & 3) * 2;
    #pragma unroll
    for (int mf = 0; mf < 2; ++mf) {
        #pragma unroll
        for (int nf = 0; nf < 8; ++nf) {
            const int r = row0 + mf * 16;
            const int c = col0 + nf * 8;
            const float b0 = __ldg(bias + c);
            const float b1 = __ldg(bias + c + 1);
            float2 v0 = make_float2(acc[mf][nf][0] + b0, acc[mf][nf][1] + b1);
            float2 v1 = make_float2(acc[mf][nf][2] + b0, acc[mf][nf][3] + b1);
            *(float2*)(out + (size_t)r * NN + c) = v0;
            *(float2*)(out + (size_t)(r + 8) * NN + c) = v1;
        }
    }
}

// ================= launch =================
extern "C" void kernel_launch(void* const* d_in, const int* in_sizes, int n_in,
                              void* d_out, int out_size)
{
    const float* x          = (const float*)d_in[0];  // (B, 1024)
    const float* perm_logit = (const float*)d_in[1];  // (DEPTH, 3)
    const float* abcd       = (const float*)d_in[2];  // (DEPTH, 4092, 2)
    const float* bias       = (const float*)d_in[3];  // (1024,)
    float* out = (float*)d_out;

    int Bn = in_sizes[0] / NN;
    int depth = in_sizes[1] / 3;

    // 1) M from butterfly on identity
    butterfly_ident_kernel<<<NN, BT>>>(perm_logit, abcd, depth);
    // 2) W -> transposed bf16 split
    convW_kernel<<<dim3(32, 32), dim3(32, 8)>>>();
    // 3) x -> bf16 split
    int n4 = Bn * NN / 4;
    convX_kernel<<<(n4 + 255) / 256, 256>>>(x, n4);
    // 4) HMMA GEMM, 3-pass accumulation in one kernel
    gemm_kernel<<<dim3(NN / TN, Bn / TM), 256>>>(bias, out);
}

// round 8
// speedup vs baseline: 2.0115x; 1.0240x over previous
#include <cuda_runtime.h>
#include <cuda_bf16.h>
#include <math.h>
#include <stdint.h>

#define NN 1024
#define BT 256  // threads for butterfly kernel

// ---------------- scratch (__device__ globals; no runtime alloc) ----------------
__device__ float          g_W[NN * NN];            // 4 MB : M[k][n] (row k = butterfly(e_k))
__device__ __nv_bfloat16  g_BhT[NN * NN];          // 2 MB : hi,  [n][k]
__device__ __nv_bfloat16  g_BlT[NN * NN];          // 2 MB : lo residual, [n][k]
__device__ __nv_bfloat16  g_xh[16384 * NN];        // 32 MB
__device__ __nv_bfloat16  g_xl[16384 * NN];        // 32 MB

// ---------------- PTX helpers (all family-agnostic: sm_80+ features) ----------------
__device__ __forceinline__ uint32_t smem_u32(const void* p) {
    uint32_t a;
    asm("{ .reg .u64 t; cvta.to.shared.u64 t, %1; cvt.u32.u64 %0, t; }" : "=r"(a) : "l"(p));
    return a;
}
#define CP_ASYNC16(s, g) \
    asm volatile("cp.async.cg.shared.global [%0], [%1], 16;" :: "r"(s), "l"(g))
#define CP_COMMIT() asm volatile("cp.async.commit_group;" ::: "memory")
#define CP_WAIT1()  asm volatile("cp.async.wait_group 1;" ::: "memory")
#define CP_WAIT0()  asm volatile("cp.async.wait_group 0;" ::: "memory")
#define LDSM4(r, addr) \
    asm volatile("ldmatrix.sync.aligned.m8n8.x4.shared.b16 {%0,%1,%2,%3}, [%4];" \
        : "=r"((r)[0]), "=r"((r)[1]), "=r"((r)[2]), "=r"((r)[3]) : "r"(addr))
#define MMA16816(d, a, b) \
    asm volatile("mma.sync.aligned.m16n8k16.row.col.f32.bf16.bf16.f32 " \
        "{%0,%1,%2,%3}, {%4,%5,%6,%7}, {%8,%9}, {%0,%1,%2,%3};" \
        : "+f"((d)[0]), "+f"((d)[1]), "+f"((d)[2]), "+f"((d)[3]) \
        : "r"((a)[0]), "r"((a)[1]), "r"((a)[2]), "r"((a)[3]), "r"((b)[0]), "r"((b)[1]))

// ================= butterfly on identity rows -> g_W =================
__global__ __launch_bounds__(BT) void butterfly_ident_kernel(
    const float* __restrict__ perm_logit, const float* __restrict__ abcd, int depth)
{
    __shared__ float2 buf[2][NN];
    const int row = blockIdx.x;
    const int t = threadIdx.x;
    #pragma unroll
    for (int u = 0; u < NN / BT; ++u) {
        int i = t + u * BT;
        buf[0][i] = make_float2(i == row ? 1.0f : 0.0f, 0.0f);
    }
    int cur = 0;
    __syncthreads();

    for (int d = 0; d < depth; ++d) {
        const float p0 = 1.0f / (1.0f + expf(-perm_logit[d * 3 + 0]));
        const float p1 = 1.0f / (1.0f + expf(-perm_logit[d * 3 + 1]));
        const float p2 = 1.0f / (1.0f + expf(-perm_logit[d * 3 + 2]));
        for (int m = 4; m <= NN; m <<= 1) {
            const int half = m >> 1;
            const int nxt = cur ^ 1;
            #pragma unroll
            for (int u = 0; u < NN / BT; ++u) {
                int i = t + u * BT;
                int blk = i & ~(m - 1);
                int j = i - blk;
                bool second = (j >= half);
                float pr = second ? p2 : p1;
                int sj  = second ? (2 * (j - half) + 1) : (2 * j);
                int rj  = second ? (m + half - 1 - j)   : (half - 1 - j);
                int srj = second ? (2 * (rj - half) + 1) : (2 * rj);
                float2 a  = buf[cur][blk + j];
                float2 bb = buf[cur][blk + sj];
                float2 c  = buf[cur][blk + rj];
                float2 dd = buf[cur][blk + srj];
                float ex = a.x + p0 * (bb.x - a.x);
                float ey = a.y + p0 * (bb.y - a.y);
                float fx = c.x + p0 * (dd.x - c.x);
                float fy = c.y + p0 * (dd.y - c.y);
                buf[nxt][i] = make_float2(ex + pr * (fx - ex), ey + pr * (fy - ey));
            }
            __syncthreads();
            cur = nxt;
        }
        const float2* abd = (const float2*)(abcd) + (size_t)d * (4 * NN - 4);
        int lh = 0;
        for (int m = 2; m <= NN; m <<= 1, ++lh) {
            const int half = m >> 1;
            const float2* W = abd + (4 * NN - 4 * m);
            const int nxt = cur ^ 1;
            #pragma unroll
            for (int u = 0; u < (NN / 2) / BT; ++u) {
                int p  = t + u * BT;
                int bi = p >> lh;
                int k  = p & (half - 1);
                int i0 = bi * m + k;
                int i1 = i0 + half;
                float2 x0 = buf[cur][i0];
                float2 x1 = buf[cur][i1];
                float2 A  = W[k];
                float2 Bw = W[half + k];
                float2 C  = W[2 * half + k];
                float2 D  = W[3 * half + k];
                float2 y0, y1;
                y0.x = A.x * x0.x - A.y * x0.y + Bw.x * x1.x - Bw.y * x1.y;
                y0.y = A.x * x0.y + A.y * x0.x + Bw.x * x1.y + Bw.y * x1.x;
                y1.x = C.x * x0.x - C.y * x0.y + D.x * x1.x - D.y * x1.y;
                y1.y = C.x * x0.y + C.y * x0.x + D.x * x1.y + D.y * x1.x;
                buf[nxt][i0] = y0;
                buf[nxt][i1] = y1;
            }
            __syncthreads();
            cur = nxt;
        }
    }
    #pragma unroll
    for (int u = 0; u < NN / BT; ++u) {
        int i = t + u * BT;
        g_W[(size_t)row * NN + i] = buf[cur][i].x;
    }
}

// ================= convert W -> transposed bf16 split =================
__global__ void convW_kernel()
{
    __shared__ float tile[32][33];
    int tx = threadIdx.x, ty = threadIdx.y;
    int bx = blockIdx.x, by = blockIdx.y;
    #pragma unroll
    for (int k = 0; k < 4; ++k) {
        int krow = by * 32 + ty + 8 * k;
        tile[ty + 8 * k][tx] = g_W[(size_t)krow * NN + bx * 32 + tx];
    }
    __syncthreads();
    #pragma unroll
    for (int k = 0; k < 4; ++k) {
        int n  = bx * 32 + ty + 8 * k;
        int kk = by * 32 + tx;
        float v = tile[tx][ty + 8 * k];
        __nv_bfloat16 h = __float2bfloat16(v);
        float r = v - __bfloat162float(h);
        g_BhT[(size_t)n * NN + kk] = h;
        g_BlT[(size_t)n * NN + kk] = __float2bfloat16(r);
    }
}

// ================= convert x -> bf16 split =================
__global__ void convX_kernel(const float* __restrict__ x, int n4)
{
    int i = blockIdx.x * blockDim.x + threadIdx.x;
    if (i >= n4) return;
    float4 v = ((const float4*)x)[i];
    __nv_bfloat16 h0 = __float2bfloat16(v.x);
    __nv_bfloat16 h1 = __float2bfloat16(v.y);
    __nv_bfloat16 h2 = __float2bfloat16(v.z);
    __nv_bfloat16 h3 = __float2bfloat16(v.w);
    __nv_bfloat162* dh = (__nv_bfloat162*)g_xh + i * 2;
    __nv_bfloat162* dl = (__nv_bfloat162*)g_xl + i * 2;
    dh[0] = __nv_bfloat162(h0, h1);
    dh[1] = __nv_bfloat162(h2, h3);
    dl[0] = __nv_bfloat162(__float2bfloat16(v.x - __bfloat162float(h0)),
                           __float2bfloat16(v.y - __bfloat162float(h1)));
    dl[1] = __nv_bfloat162(__float2bfloat16(v.z - __bfloat162float(h2)),
                           __float2bfloat16(v.w - __bfloat162float(h3)));
}

// ================= HMMA GEMM: out = xh*Wh + xh*Wl + xl*Wh + bias =================
// CTA tile 128x128, K-stage 32. 3-stage cp.async ring in dynamic smem, ONE
// __syncthreads per stage; next-stage issue placed after the barrier and before
// the MMAs so global latency hides behind a full stage of tensor work.
// Smem rows padded to 40 bf16 (80B) -> conflict-free ldmatrix.
#define TM 128
#define TN 128
#define TK 32
#define PAD 40
#define AST (TM * PAD)                  // bf16 elems per A stage (5120)
#define BST (TN * PAD)
#define NRING 3
#define ABYTES (AST * 2)                // 10240 B
#define BBYTES (BST * 2)
#define SMEM_GEMM (NRING * (ABYTES + BBYTES))   // 61440 B
#define CHUNKS_PER_PASS (NN / TK)       // 32
#define NSTAGES_TOT (3 * CHUNKS_PER_PASS)  // 96

__global__ __launch_bounds__(256) void gemm_kernel(
    const float* __restrict__ bias, float* __restrict__ out)
{
    extern __shared__ __nv_bfloat16 smem[];
    __nv_bfloat16* As = smem;                       // NRING stages of A
    __nv_bfloat16* Bs = smem + NRING * AST;         // NRING stages of B

    const int tid = threadIdx.x;
    const int lane = tid & 31;
    const int wid = tid >> 5;
    const int wm = wid & 3;       // 4 warps over M (32 rows each)
    const int wn = wid >> 2;      // 2 warps over N (64 cols each)
    const int gn = blockIdx.x;    // N block (fast) -> A reuse in L2
    const int gm = blockIdx.y;    // M block

    float acc[2][8][4];
    #pragma unroll
    for (int mf = 0; mf < 2; ++mf)
        #pragma unroll
        for (int nf = 0; nf < 8; ++nf)
            #pragma unroll
            for (int q = 0; q < 4; ++q) acc[mf][nf][q] = 0.0f;

    const uint32_t sAbase = smem_u32(As);
    const uint32_t sBbase = smem_u32(Bs);

    // cp.async mapping: 512 16B-chunks per tile; thread t handles chunks t and t+256.
    const int r0  = tid >> 2;           // row 0..63
    const int cc0 = tid & 3;            // 16B chunk within 64B row window
    const uint32_t w0 = (uint32_t)(r0 * 80 + cc0 * 16);
    const uint32_t w1 = w0 + 64 * 80;

    const __nv_bfloat16* const Aps[3] = { g_xh, g_xh, g_xl };
    const __nv_bfloat16* const Bps[3] = { g_BhT, g_BlT, g_BhT };

    auto issue = [&](int s, int slot) {
        const int pass = s >> 5;                       // 32 chunks per pass
        const int k0 = (s & (CHUNKS_PER_PASS - 1)) * TK;
        const __nv_bfloat16* Ap = Aps[pass] + (size_t)(gm * TM) * NN + k0;
        const __nv_bfloat16* Bp = Bps[pass] + (size_t)(gn * TN) * NN + k0;
        const uint32_t sa = sAbase + (uint32_t)(slot * ABYTES);
        const uint32_t sb = sBbase + (uint32_t)(slot * BBYTES);
        CP_ASYNC16(sa + w0, Ap + (size_t)r0 * NN + cc0 * 8);
        CP_ASYNC16(sa + w1, Ap + (size_t)(r0 + 64) * NN + cc0 * 8);
        CP_ASYNC16(sb + w0, Bp + (size_t)r0 * NN + cc0 * 8);
        CP_ASYNC16(sb + w1, Bp + (size_t)(r0 + 64) * NN + cc0 * 8);
        CP_COMMIT();
    };

    // ldmatrix lane address components
    const int a_r = (lane & 7) | (((lane >> 3) & 1) << 3);   // row 0..15 within frag
    const int a_c = ((lane >> 4) & 1) * 8;                   // +8 elems for mats 2,3
    const int b_n = (lane & 7) | (((lane >> 4) & 1) << 3);   // n row within 16
    const int b_k = ((lane >> 3) & 1) * 8;                   // +8 elems for mats 1,3
    const uint32_t aoff = (uint32_t)((wm * 32 + a_r) * 80 + a_c * 2);
    const uint32_t boff = (uint32_t)((wn * 64 + b_n) * 80 + b_k * 2);

    // prologue: 2 stages in flight
    issue(0, 0);
    issue(1, 1);

    int slot = 0, islot = 2;   // compute slot; next issue slot
    for (int s = 0; s < NSTAGES_TOT; ++s) {
        if (s == NSTAGES_TOT - 1) { CP_WAIT0(); }
        else                      { CP_WAIT1(); }
        __syncthreads();   // stage s visible to all; all warps done with stage s-1's slot
        if (s + 2 < NSTAGES_TOT) {
            issue(s + 2, islot);
            if (++islot == NRING) islot = 0;
        }
        const uint32_t sa = sAbase + (uint32_t)(slot * ABYTES) + aoff;
        const uint32_t sb = sBbase + (uint32_t)(slot * BBYTES) + boff;
        if (++slot == NRING) slot = 0;
        #pragma unroll
        for (int kk = 0; kk < 2; ++kk) {
            uint32_t af[2][4];
            LDSM4(af[0], sa + kk * 32);
            LDSM4(af[1], sa + kk * 32 + 16 * 80);
            uint32_t bfr[4][4];
            #pragma unroll
            for (int g2 = 0; g2 < 4; ++g2)
                LDSM4(bfr[g2], sb + kk * 32 + g2 * 16 * 80);
            #pragma unroll
            for (int mf = 0; mf < 2; ++mf)
                #pragma unroll
                for (int nf = 0; nf < 8; ++nf) {
                    uint32_t bb[2] = { bfr[nf >> 1][(nf & 1) * 2],
                                       bfr[nf >> 1][(nf & 1) * 2 + 1] };
                    MMA16816(acc[mf][nf], af[mf], bb);
                }
        }
    }

    // epilogue: add bias, store fp32
    const int row0 = gm * TM + wm * 32 + (lane >> 2);
    const int col0 = gn * TN + wn * 64 + (lane & 3) * 2;
    #pragma unroll
    for (int mf = 0; mf < 2; ++mf) {
        #pragma unroll
        for (int nf = 0; nf < 8; ++nf) {
            const int r = row0 + mf * 16;
            const int c = col0 + nf * 8;
            const float b0 = __ldg(bias + c);
            const float b1 = __ldg(bias + c + 1);
            float2 v0 = make_float2(acc[mf][nf][0] + b0, acc[mf][nf][1] + b1);
            float2 v1 = make_float2(acc[mf][nf][2] + b0, acc[mf][nf][3] + b1);
            *(float2*)(out + (size_t)r * NN + c) = v0;
            *(float2*)(out + (size_t)(r + 8) * NN + c) = v1;
        }
    }
}

// ================= launch =================
extern "C" void kernel_launch(void* const* d_in, const int* in_sizes, int n_in,
                              void* d_out, int out_size)
{
    const float* x          = (const float*)d_in[0];  // (B, 1024)
    const float* perm_logit = (const float*)d_in[1];  // (DEPTH, 3)
    const float* abcd       = (const float*)d_in[2];  // (DEPTH, 4092, 2)
    const float* bias       = (const float*)d_in[3];  // (1024,)
    float* out = (float*)d_out;

    int Bn = in_sizes[0] / NN;
    int depth = in_sizes[1] / 3;

    static bool attr_set = false;
    if (!attr_set) {
        cudaFuncSetAttribute(gemm_kernel, cudaFuncAttributeMaxDynamicSharedMemorySize, SMEM_GEMM);
        attr_set = true;
    }

    // 1) M from butterfly on identity
    butterfly_ident_kernel<<<NN, BT>>>(perm_logit, abcd, depth);
    // 2) W -> transposed bf16 split
    convW_kernel<<<dim3(32, 32), dim3(32, 8)>>>();
    // 3) x -> bf16 split
    int n4 = Bn * NN / 4;
    convX_kernel<<<(n4 + 255) / 256, 256>>>(x, n4);
    // 4) HMMA GEMM, 3-pass accumulation, 3-stage pipeline
    gemm_kernel<<<dim3(NN / TN, Bn / TM), 256, SMEM_GEMM>>>(bias, out);
}

// round 9
// speedup vs baseline: 2.6540x; 1.3194x over previous
#include <cuda_runtime.h>
#include <cuda_fp16.h>
#include <math.h>
#include <stdint.h>

#define NN 1024
#define BT 256  // threads for butterfly kernel

// ---------------- scratch (__device__ globals; no runtime alloc) ----------------
__device__ float   g_W[NN * NN];            // 4 MB : M[k][n] (row k = butterfly(e_k))
__device__ __half  g_WhT[NN * NN];          // 2 MB : fp16(W), transposed [n][k]
__device__ __half  g_xh[16384 * NN];        // 32 MB : fp16(x)
__device__ __half  g_xl[16384 * NN];        // 32 MB : fp16(x - xh)

// ---------------- PTX helpers (all family-agnostic: sm_80+ features) ----------------
__device__ __forceinline__ uint32_t smem_u32(const void* p) {
    uint32_t a;
    asm("{ .reg .u64 t; cvta.to.shared.u64 t, %1; cvt.u32.u64 %0, t; }" : "=r"(a) : "l"(p));
    return a;
}
#define CP_ASYNC16(s, g) \
    asm volatile("cp.async.cg.shared.global [%0], [%1], 16;" :: "r"(s), "l"(g))
#define CP_COMMIT() asm volatile("cp.async.commit_group;" ::: "memory")
#define CP_WAIT1()  asm volatile("cp.async.wait_group 1;" ::: "memory")
#define CP_WAIT0()  asm volatile("cp.async.wait_group 0;" ::: "memory")
#define LDSM4(r, addr) \
    asm volatile("ldmatrix.sync.aligned.m8n8.x4.shared.b16 {%0,%1,%2,%3}, [%4];" \
        : "=r"((r)[0]), "=r"((r)[1]), "=r"((r)[2]), "=r"((r)[3]) : "r"(addr))
#define MMA16816(d, a, b) \
    asm volatile("mma.sync.aligned.m16n8k16.row.col.f32.f16.f16.f32 " \
        "{%0,%1,%2,%3}, {%4,%5,%6,%7}, {%8,%9}, {%0,%1,%2,%3};" \
        : "+f"((d)[0]), "+f"((d)[1]), "+f"((d)[2]), "+f"((d)[3]) \
        : "r"((a)[0]), "r"((a)[1]), "r"((a)[2]), "r"((a)[3]), "r"((b)[0]), "r"((b)[1]))

// ================= butterfly on identity rows -> g_W =================
__global__ __launch_bounds__(BT) void butterfly_ident_kernel(
    const float* __restrict__ perm_logit, const float* __restrict__ abcd, int depth)
{
    __shared__ float2 buf[2][NN];
    const int row = blockIdx.x;
    const int t = threadIdx.x;
    #pragma unroll
    for (int u = 0; u < NN / BT; ++u) {
        int i = t + u * BT;
        buf[0][i] = make_float2(i == row ? 1.0f : 0.0f, 0.0f);
    }
    int cur = 0;
    __syncthreads();

    for (int d = 0; d < depth; ++d) {
        const float p0 = 1.0f / (1.0f + expf(-perm_logit[d * 3 + 0]));
        const float p1 = 1.0f / (1.0f + expf(-perm_logit[d * 3 + 1]));
        const float p2 = 1.0f / (1.0f + expf(-perm_logit[d * 3 + 2]));
        for (int m = 4; m <= NN; m <<= 1) {
            const int half = m >> 1;
            const int nxt = cur ^ 1;
            #pragma unroll
            for (int u = 0; u < NN / BT; ++u) {
                int i = t + u * BT;
                int blk = i & ~(m - 1);
                int j = i - blk;
                bool second = (j >= half);
                float pr = second ? p2 : p1;
                int sj  = second ? (2 * (j - half) + 1) : (2 * j);
                int rj  = second ? (m + half - 1 - j)   : (half - 1 - j);
                int srj = second ? (2 * (rj - half) + 1) : (2 * rj);
                float2 a  = buf[cur][blk + j];
                float2 bb = buf[cur][blk + sj];
                float2 c  = buf[cur][blk + rj];
                float2 dd = buf[cur][blk + srj];
                float ex = a.x + p0 * (bb.x - a.x);
                float ey = a.y + p0 * (bb.y - a.y);
                float fx = c.x + p0 * (dd.x - c.x);
                float fy = c.y + p0 * (dd.y - c.y);
                buf[nxt][i] = make_float2(ex + pr * (fx - ex), ey + pr * (fy - ey));
            }
            __syncthreads();
            cur = nxt;
        }
        const float2* abd = (const float2*)(abcd) + (size_t)d * (4 * NN - 4);
        int lh = 0;
        for (int m = 2; m <= NN; m <<= 1, ++lh) {
            const int half = m >> 1;
            const float2* W = abd + (4 * NN - 4 * m);
            const int nxt = cur ^ 1;
            #pragma unroll
            for (int u = 0; u < (NN / 2) / BT; ++u) {
                int p  = t + u * BT;
                int bi = p >> lh;
                int k  = p & (half - 1);
                int i0 = bi * m + k;
                int i1 = i0 + half;
                float2 x0 = buf[cur][i0];
                float2 x1 = buf[cur][i1];
                float2 A  = W[k];
                float2 Bw = W[half + k];
                float2 C  = W[2 * half + k];
                float2 D  = W[3 * half + k];
                float2 y0, y1;
                y0.x = A.x * x0.x - A.y * x0.y + Bw.x * x1.x - Bw.y * x1.y;
                y0.y = A.x * x0.y + A.y * x0.x + Bw.x * x1.y + Bw.y * x1.x;
                y1.x = C.x * x0.x - C.y * x0.y + D.x * x1.x - D.y * x1.y;
                y1.y = C.x * x0.y + C.y * x0.x + D.x * x1.y + D.y * x1.x;
                buf[nxt][i0] = y0;
                buf[nxt][i1] = y1;
            }
            __syncthreads();
            cur = nxt;
        }
    }
    #pragma unroll
    for (int u = 0; u < NN / BT; ++u) {
        int i = t + u * BT;
        g_W[(size_t)row * NN + i] = buf[cur][i].x;
    }
}

// ================= convert W -> transposed fp16 =================
__global__ void convW_kernel()
{
    __shared__ float tile[32][33];
    int tx = threadIdx.x, ty = threadIdx.y;
    int bx = blockIdx.x, by = blockIdx.y;
    #pragma unroll
    for (int k = 0; k < 4; ++k) {
        int krow = by * 32 + ty + 8 * k;
        tile[ty + 8 * k][tx] = g_W[(size_t)krow * NN + bx * 32 + tx];
    }
    __syncthreads();
    #pragma unroll
    for (int k = 0; k < 4; ++k) {
        int n  = bx * 32 + ty + 8 * k;
        int kk = by * 32 + tx;
        g_WhT[(size_t)n * NN + kk] = __float2half(tile[tx][ty + 8 * k]);
    }
}

// ================= convert x -> fp16 split (xh + xl ~ 22-bit x) =================
__global__ void convX_kernel(const float* __restrict__ x, int n4)
{
    int i = blockIdx.x * blockDim.x + threadIdx.x;
    if (i >= n4) return;
    float4 v = ((const float4*)x)[i];
    __half h0 = __float2half(v.x);
    __half h1 = __float2half(v.y);
    __half h2 = __float2half(v.z);
    __half h3 = __float2half(v.w);
    __half2* dh = (__half2*)g_xh + i * 2;
    __half2* dl = (__half2*)g_xl + i * 2;
    dh[0] = __half2(h0, h1);
    dh[1] = __half2(h2, h3);
    dl[0] = __half2(__float2half(v.x - __half2float(h0)),
                    __float2half(v.y - __half2float(h1)));
    dl[1] = __half2(__float2half(v.z - __half2float(h2)),
                    __float2half(v.w - __half2float(h3)));
}

// ================= HMMA GEMM: out = xh*Wh + xl*Wh + bias =================
// CTA tile 128x128, K-stage 32. 3-stage cp.async ring in dynamic smem, one
// __syncthreads per stage; next-stage issue after the barrier, before the MMAs.
// Smem rows padded to 40 halves (80B) -> conflict-free ldmatrix.
#define TM 128
#define TN 128
#define TK 32
#define PAD 40
#define AST (TM * PAD)                  // half elems per A stage (5120)
#define BST (TN * PAD)
#define NRING 3
#define ABYTES (AST * 2)                // 10240 B
#define BBYTES (BST * 2)
#define SMEM_GEMM (NRING * (ABYTES + BBYTES))   // 61440 B
#define CHUNKS_PER_PASS (NN / TK)       // 32
#define NPASSES 2
#define NSTAGES_TOT (NPASSES * CHUNKS_PER_PASS)  // 64

__global__ __launch_bounds__(256) void gemm_kernel(
    const float* __restrict__ bias, float* __restrict__ out)
{
    extern __shared__ __half smem[];
    __half* As = smem;                       // NRING stages of A
    __half* Bs = smem + NRING * AST;         // NRING stages of B

    const int tid = threadIdx.x;
    const int lane = tid & 31;
    const int wid = tid >> 5;
    const int wm = wid & 3;       // 4 warps over M (32 rows each)
    const int wn = wid >> 2;      // 2 warps over N (64 cols each)
    const int gn = blockIdx.x;    // N block (fast) -> A reuse in L2
    const int gm = blockIdx.y;    // M block

    float acc[2][8][4];
    #pragma unroll
    for (int mf = 0; mf < 2; ++mf)
        #pragma unroll
        for (int nf = 0; nf < 8; ++nf)
            #pragma unroll
            for (int q = 0; q < 4; ++q) acc[mf][nf][q] = 0.0f;

    const uint32_t sAbase = smem_u32(As);
    const uint32_t sBbase = smem_u32(Bs);

    // cp.async mapping: 512 16B-chunks per tile; thread t handles chunks t and t+256.
    const int r0  = tid >> 2;           // row 0..63
    const int cc0 = tid & 3;            // 16B chunk within 64B row window
    const uint32_t w0 = (uint32_t)(r0 * 80 + cc0 * 16);
    const uint32_t w1 = w0 + 64 * 80;

    const __half* const Aps[NPASSES] = { g_xh, g_xl };

    auto issue = [&](int s, int slot) {
        const int pass = s >> 5;                       // 32 chunks per pass
        const int k0 = (s & (CHUNKS_PER_PASS - 1)) * TK;
        const __half* Ap = Aps[pass] + (size_t)(gm * TM) * NN + k0;
        const __half* Bp = g_WhT + (size_t)(gn * TN) * NN + k0;
        const uint32_t sa = sAbase + (uint32_t)(slot * ABYTES);
        const uint32_t sb = sBbase + (uint32_t)(slot * BBYTES);
        CP_ASYNC16(sa + w0, Ap + (size_t)r0 * NN + cc0 * 8);
        CP_ASYNC16(sa + w1, Ap + (size_t)(r0 + 64) * NN + cc0 * 8);
        CP_ASYNC16(sb + w0, Bp + (size_t)r0 * NN + cc0 * 8);
        CP_ASYNC16(sb + w1, Bp + (size_t)(r0 + 64) * NN + cc0 * 8);
        CP_COMMIT();
    };

    // ldmatrix lane address components
    const int a_r = (lane & 7) | (((lane >> 3) & 1) << 3);   // row 0..15 within frag
    const int a_c = ((lane >> 4) & 1) * 8;                   // +8 elems for mats 2,3
    const int b_n = (lane & 7) | (((lane >> 4) & 1) << 3);   // n row within 16
    const int b_k = ((lane >> 3) & 1) * 8;                   // +8 elems for mats 1,3
    const uint32_t aoff = (uint32_t)((wm * 32 + a_r) * 80 + a_c * 2);
    const uint32_t boff = (uint32_t)((wn * 64 + b_n) * 80 + b_k * 2);

    // prologue: 2 stages in flight
    issue(0, 0);
    issue(1, 1);

    int slot = 0, islot = 2;   // compute slot; next issue slot
    for (int s = 0; s < NSTAGES_TOT; ++s) {
        if (s == NSTAGES_TOT - 1) { CP_WAIT0(); }
        else                      { CP_WAIT1(); }
        __syncthreads();   // stage s visible; all warps done with previous use of slot
        if (s + 2 < NSTAGES_TOT) {
            issue(s + 2, islot);
            if (++islot == NRING) islot = 0;
        }
        const uint32_t sa = sAbase + (uint32_t)(slot * ABYTES) + aoff;
        const uint32_t sb = sBbase + (uint32_t)(slot * BBYTES) + boff;
        if (++slot == NRING) slot = 0;
        #pragma unroll
        for (int kk = 0; kk < 2; ++kk) {
            uint32_t af[2][4];
            LDSM4(af[0], sa + kk * 32);
            LDSM4(af[1], sa + kk * 32 + 16 * 80);
            uint32_t bfr[4][4];
            #pragma unroll
            for (int g2 = 0; g2 < 4; ++g2)
                LDSM4(bfr[g2], sb + kk * 32 + g2 * 16 * 80);
            #pragma unroll
            for (int mf = 0; mf < 2; ++mf)
                #pragma unroll
                for (int nf = 0; nf < 8; ++nf) {
                    uint32_t bb[2] = { bfr[nf >> 1][(nf & 1) * 2],
                                       bfr[nf >> 1][(nf & 1) * 2 + 1] };
                    MMA16816(acc[mf][nf], af[mf], bb);
                }
        }
    }

    // epilogue: add bias, store fp32
    const int row0 = gm * TM + wm * 32 + (lane >> 2);
    const int col0 = gn * TN + wn * 64 + (lane & 3) * 2;
    #pragma unroll
    for (int mf = 0; mf < 2; ++mf) {
        #pragma unroll
        for (int nf = 0; nf < 8; ++nf) {
            const int r = row0 + mf * 16;
            const int c = col0 + nf * 8;
            const float b0 = __ldg(bias + c);
            const float b1 = __ldg(bias + c + 1);
            float2 v0 = make_float2(acc[mf][nf][0] + b0, acc[mf][nf][1] + b1);
            float2 v1 = make_float2(acc[mf][nf][2] + b0, acc[mf][nf][3] + b1);
            *(float2*)(out + (size_t)r * NN + c) = v0;
            *(float2*)(out + (size_t)(r + 8) * NN + c) = v1;
        }
    }
}

// ================= launch =================
extern "C" void kernel_launch(void* const* d_in, const int* in_sizes, int n_in,
                              void* d_out, int out_size)
{
    const float* x          = (const float*)d_in[0];  // (B, 1024)
    const float* perm_logit = (const float*)d_in[1];  // (DEPTH, 3)
    const float* abcd       = (const float*)d_in[2];  // (DEPTH, 4092, 2)
    const float* bias       = (const float*)d_in[3];  // (1024,)
    float* out = (float*)d_out;

    int Bn = in_sizes[0] / NN;
    int depth = in_sizes[1] / 3;

    static bool attr_set = false;
    if (!attr_set) {
        cudaFuncSetAttribute(gemm_kernel, cudaFuncAttributeMaxDynamicSharedMemorySize, SMEM_GEMM);
        attr_set = true;
    }

    // 1) M from butterfly on identity
    butterfly_ident_kernel<<<NN, BT>>>(perm_logit, abcd, depth);
    // 2) W -> transposed fp16
    convW_kernel<<<dim3(32, 32), dim3(32, 8)>>>();
    // 3) x -> fp16 split (xh + xl)
    int n4 = Bn * NN / 4;
    convX_kernel<<<(n4 + 255) / 256, 256>>>(x, n4);
    // 4) HMMA GEMM, 2-pass accumulation, 3-stage pipeline
    gemm_kernel<<<dim3(NN / TN, Bn / TM), 256, SMEM_GEMM>>>(bias, out);
}